// round 7
// baseline (speedup 1.0000x reference)
#include <cuda_runtime.h>
#include <cstdint>

// PosRegressor_43482248904949 — batched bilinear shift with mirror boundary.
// images: (256,512,512,1) fp32, dxdy: (256,2) fp32 -> out: (256,512,512) fp32.
//
// R7: vectorized I/O. dx,dy per-image scalars => integer shift (kx,ky) +
// constant weights (fx,fy). Misalignment m = kx mod 4 is UNIFORM across
// threads => one uniform switch, static register window select.
// Thread = 4 aligned output cols x 4 rows:
//   per input row: 2 overlapping LDG.128 (2nd is L1 hit), 4 FMA
//   per output row: 1 STG.128
// Cuts LSU issue cycles ~2x vs R6 scalar version (36 LDG + 16 STG.32/warp).

#define H 512
#define W 512
#define NTHREADS 256

__device__ __forceinline__ int mirror_idx(int idx, int n) {
    const int p = 2 * (n - 1);
    int i = idx < 0 ? -idx : idx;
    i %= p;
    return (i >= n) ? (p - i) : i;
}

template <int M>
__device__ __forceinline__ void run_tile(
    const float* __restrict__ imb,   // image base for this b
    float* __restrict__ outp,        // output ptr: first row, this thread's quad
    int r0, int r1, int r2, int r3, int r4,   // mirrored input row offsets (elems)
    int a0,                          // aligned input start column (may be OOB)
    float fx, float fy)
{
    float h[5][4];
    const int roff[5] = {r0, r1, r2, r3, r4};
    #pragma unroll
    for (int r = 0; r < 5; ++r) {
        const float* __restrict__ row = imb + roff[r];
        float v[8];
        if (a0 >= 0 && a0 + 7 < W) {
            const float4 A = *reinterpret_cast<const float4*>(row + a0);
            const float4 B = *reinterpret_cast<const float4*>(row + a0 + 4);
            v[0]=A.x; v[1]=A.y; v[2]=A.z; v[3]=A.w;
            v[4]=B.x; v[5]=B.y; v[6]=B.z; v[7]=B.w;
        } else {
            #pragma unroll
            for (int e = 0; e < 8; ++e)
                v[e] = row[mirror_idx(a0 + e, W)];
        }
        #pragma unroll
        for (int j = 0; j < 4; ++j)
            h[r][j] = fmaf(fx, v[M + j + 1] - v[M + j], v[M + j]);
    }
    #pragma unroll
    for (int r = 0; r < 4; ++r) {
        float4 o;
        o.x = fmaf(fy, h[r + 1][0] - h[r][0], h[r][0]);
        o.y = fmaf(fy, h[r + 1][1] - h[r][1], h[r][1]);
        o.z = fmaf(fy, h[r + 1][2] - h[r][2], h[r][2]);
        o.w = fmaf(fy, h[r + 1][3] - h[r][3], h[r][3]);
        *reinterpret_cast<float4*>(outp) = o;
        outp += W;
    }
}

__global__ void __launch_bounds__(NTHREADS, 5)
shift_bilinear_kernel(const float* __restrict__ img,
                      const float* __restrict__ dxdy,
                      float* __restrict__ out) {
    const int b    = blockIdx.y;
    const int yb   = blockIdx.x * 8;        // 8 output rows per block
    const int tid  = threadIdx.x;
    const int wid  = tid >> 5;
    const int lane = tid & 31;

    const int cw = (wid & 3) * 128;         // warp column tile
    const int h0 = (wid >> 2) * 4;          // row half: rows [h0, h0+4)

    const float dy = dxdy[2 * b + 0];
    const float dx = dxdy[2 * b + 1];
    const float ndx = -dx, ndy = -dy;
    const float kxf = floorf(ndx); const int kx = (int)kxf; const float fx = ndx - kxf;
    const float kyf = floorf(ndy); const int ky = (int)kyf; const float fy = ndy - kyf;

    const int m  = kx & 3;                  // uniform across all threads
    const int a0 = cw + 4 * lane + kx - m;  // 4-aligned input start

    const size_t base = (size_t)b * (H * W);
    const float* __restrict__ imb = img + base;
    float* __restrict__ outp = out + base + (size_t)(yb + h0) * W + cw + 4 * lane;

    const int ybase = yb + ky + h0;
    const int r0 = mirror_idx(ybase,     H) * W;
    const int r1 = mirror_idx(ybase + 1, H) * W;
    const int r2 = mirror_idx(ybase + 2, H) * W;
    const int r3 = mirror_idx(ybase + 3, H) * W;
    const int r4 = mirror_idx(ybase + 4, H) * W;

    switch (m) {
        case 0: run_tile<0>(imb, outp, r0, r1, r2, r3, r4, a0, fx, fy); break;
        case 1: run_tile<1>(imb, outp, r0, r1, r2, r3, r4, a0, fx, fy); break;
        case 2: run_tile<2>(imb, outp, r0, r1, r2, r3, r4, a0, fx, fy); break;
        default: run_tile<3>(imb, outp, r0, r1, r2, r3, r4, a0, fx, fy); break;
    }
}

extern "C" void kernel_launch(void* const* d_in, const int* in_sizes, int n_in,
                              void* d_out, int out_size) {
    const float* images = (const float*)d_in[0];  // (256,512,512,1)
    const float* dxdy   = (const float*)d_in[1];  // (256,2)
    float* out = (float*)d_out;                   // (256,512,512)

    const int B = in_sizes[1] / 2;                // 256
    dim3 grid(H / 8, B);
    shift_bilinear_kernel<<<grid, NTHREADS>>>(images, dxdy, out);
}

// round 8
// speedup vs baseline: 1.1137x; 1.1137x over previous
#include <cuda_runtime.h>
#include <cstdint>

// PosRegressor_43482248904949 — batched bilinear shift with mirror boundary.
// images: (256,512,512,1) fp32, dxdy: (256,2) fp32 -> out: (256,512,512) fp32.
//
// R8: R7 vectorized structure + restored MLP + L2-friendly stores.
//  - launch_bounds(256,4) => 64-reg budget: all 10 row-loads (5 rows x 2
//    overlapping LDG.128) issued before any compute -> deep per-thread MLP.
//  - __stcs streaming stores: output never re-read; keep L2 for the
//    input row-overlap reuse (intra-block +1 row, cross-block boundary row).
//  - uniform m = kx mod 4 selects the register window (no divergence).

#define H 512
#define W 512
#define NTHREADS 256

__device__ __forceinline__ int mirror_idx(int idx, int n) {
    const int p = 2 * (n - 1);
    int i = idx < 0 ? -idx : idx;
    i %= p;
    return (i >= n) ? (p - i) : i;
}

template <int M>
__device__ __forceinline__ void run_tile(
    const float* __restrict__ imb,
    float* __restrict__ outp,
    const int* __restrict__ roff,    // 5 mirrored input row offsets (elems)
    int a0,                          // 4-aligned input start column
    float fx, float fy)
{
    // ---- Load phase: 10 independent LDG.128 front-batched (deep MLP).
    float v[5][8];
    const bool interior = (a0 >= 0) & (a0 + 7 < W);
    if (interior) {
        #pragma unroll
        for (int r = 0; r < 5; ++r) {
            const float4 A = *reinterpret_cast<const float4*>(imb + roff[r] + a0);
            const float4 B = *reinterpret_cast<const float4*>(imb + roff[r] + a0 + 4);
            v[r][0]=A.x; v[r][1]=A.y; v[r][2]=A.z; v[r][3]=A.w;
            v[r][4]=B.x; v[r][5]=B.y; v[r][6]=B.z; v[r][7]=B.w;
        }
    } else {
        #pragma unroll
        for (int r = 0; r < 5; ++r)
            #pragma unroll
            for (int e = 0; e < 8; ++e)
                v[r][e] = imb[roff[r] + mirror_idx(a0 + e, W)];
    }

    // ---- Horizontal lerp (constant fx), window at uniform offset M.
    float h[5][4];
    #pragma unroll
    for (int r = 0; r < 5; ++r)
        #pragma unroll
        for (int j = 0; j < 4; ++j)
            h[r][j] = fmaf(fx, v[r][M + j + 1] - v[r][M + j], v[r][M + j]);

    // ---- Vertical lerp + streaming STG.128.
    #pragma unroll
    for (int r = 0; r < 4; ++r) {
        float4 o;
        o.x = fmaf(fy, h[r + 1][0] - h[r][0], h[r][0]);
        o.y = fmaf(fy, h[r + 1][1] - h[r][1], h[r][1]);
        o.z = fmaf(fy, h[r + 1][2] - h[r][2], h[r][2]);
        o.w = fmaf(fy, h[r + 1][3] - h[r][3], h[r][3]);
        __stcs(reinterpret_cast<float4*>(outp), o);
        outp += W;
    }
}

__global__ void __launch_bounds__(NTHREADS, 4)
shift_bilinear_kernel(const float* __restrict__ img,
                      const float* __restrict__ dxdy,
                      float* __restrict__ out) {
    const int b    = blockIdx.y;
    const int yb   = blockIdx.x * 8;        // 8 output rows per block
    const int tid  = threadIdx.x;
    const int wid  = tid >> 5;
    const int lane = tid & 31;

    const int cw = (wid & 3) * 128;         // warp column tile
    const int h0 = (wid >> 2) * 4;          // row half: rows [h0, h0+4)

    const float dy = dxdy[2 * b + 0];
    const float dx = dxdy[2 * b + 1];
    const float ndx = -dx, ndy = -dy;
    const float kxf = floorf(ndx); const int kx = (int)kxf; const float fx = ndx - kxf;
    const float kyf = floorf(ndy); const int ky = (int)kyf; const float fy = ndy - kyf;

    const int m  = kx & 3;                  // uniform across all threads
    const int a0 = cw + 4 * lane + kx - m;  // 4-aligned input start

    const size_t base = (size_t)b * (H * W);
    const float* __restrict__ imb = img + base;
    float* __restrict__ outp = out + base + (size_t)(yb + h0) * W + cw + 4 * lane;

    const int ybase = yb + ky + h0;
    int roff[5];
    #pragma unroll
    for (int r = 0; r < 5; ++r)
        roff[r] = mirror_idx(ybase + r, H) * W;

    switch (m) {
        case 0: run_tile<0>(imb, outp, roff, a0, fx, fy); break;
        case 1: run_tile<1>(imb, outp, roff, a0, fx, fy); break;
        case 2: run_tile<2>(imb, outp, roff, a0, fx, fy); break;
        default: run_tile<3>(imb, outp, roff, a0, fx, fy); break;
    }
}

extern "C" void kernel_launch(void* const* d_in, const int* in_sizes, int n_in,
                              void* d_out, int out_size) {
    const float* images = (const float*)d_in[0];  // (256,512,512,1)
    const float* dxdy   = (const float*)d_in[1];  // (256,2)
    float* out = (float*)d_out;                   // (256,512,512)

    const int B = in_sizes[1] / 2;                // 256
    dim3 grid(H / 8, B);
    shift_bilinear_kernel<<<grid, NTHREADS>>>(images, dxdy, out);
}